// round 7
// baseline (speedup 1.0000x reference)
#include <cuda_runtime.h>
#include <math.h>

#define B_ 32
#define S_ 2048
#define H_ 1024
#define NROWS (2 * B_ * S_)                       // 131072 reward scalars
#define WARPS_PER_BLOCK 8
#define NBLOCKS (NROWS / WARPS_PER_BLOCK)         // 16384
#define BLOCKS_PER_BATCH (S_ / WARPS_PER_BLOCK)   // 256

// Scratch (allowed: __device__ globals, no allocation). 64-bit monotonic
// counters survive graph replays (gates use modulo tests, no resets needed).
__device__ float              g_rewards[NROWS];
__device__ float              g_per_pair[B_];
__device__ int                g_accflag[B_];
__device__ unsigned long long g_batch_cnt[2 * B_];
__device__ unsigned long long g_pair_cnt[B_];
__device__ unsigned long long g_fin_cnt;

__device__ __forceinline__ float warp_sum(float v) {
#pragma unroll
    for (int o = 16; o; o >>= 1) v += __shfl_xor_sync(0xffffffffu, v, o);
    return v;
}
__device__ __forceinline__ int warp_sum_i(int v) {
#pragma unroll
    for (int o = 16; o; o >>= 1) v += __shfl_xor_sync(0xffffffffu, v, o);
    return v;
}
__device__ __forceinline__ int warp_min_i(int v) {
#pragma unroll
    for (int o = 16; o; o >>= 1) v = min(v, __shfl_xor_sync(0xffffffffu, v, o));
    return v;
}

// ---------------------------------------------------------------------------
// Single fused kernel.
//  Phase A (all blocks): 8 reward dots (one warp per row). Streaming loads.
//  Gate 1 (tid0 ONLY: syncthreads -> one threadfence -> atomics):
//    block completing the 256th chunk of a batch bumps the pair counter;
//    block completing the SECOND batch of a pair runs Phase B inline.
//  Phase B (32 scattered blocks, overlapped with dot drain): id scan +
//    smem-staged masked sigmoid sums for one pair.
//  Gate 2: 32nd pair completion runs the deterministic final reduction.
// ---------------------------------------------------------------------------
__global__ void __launch_bounds__(WARPS_PER_BLOCK * 32)
fused_kernel(const int* __restrict__ ids, const float* __restrict__ hs,
             const float* __restrict__ w, float* __restrict__ out) {
    const int tid  = threadIdx.x;
    const int warp = tid >> 5;
    const int lane = tid & 31;

    // All smem up-front, 16B-aligned where reinterpret-cast to float4.
    __shared__ __align__(16) float4 sw[H_ / 4];
    __shared__ __align__(16) float  s_rc[S_];
    __shared__ __align__(16) float  s_rr[S_];
    __shared__ int    s_pair;
    __shared__ int    sc, sr, sd;
    __shared__ float  sl[8], ss1[8], ss2[8];
    __shared__ int    sn[8];
    __shared__ bool   s_final;

    // ---- Phase A: 8 reward dots ----
    for (int i = tid; i < H_ / 4; i += blockDim.x)
        sw[i] = reinterpret_cast<const float4*>(w)[i];
    __syncthreads();

    const int row = blockIdx.x * WARPS_PER_BLOCK + warp;   // grid exact
    {
        const float4* __restrict__ hp =
            reinterpret_cast<const float4*>(hs + (size_t)row * H_);
        float acc = 0.0f;
#pragma unroll
        for (int i = 0; i < 8; i++) {
            float4 h  = __ldcs(&hp[lane + i * 32]);   // streaming, no reuse
            float4 ww = sw[lane + i * 32];
            acc += h.x * ww.x + h.y * ww.y + h.z * ww.z + h.w * ww.w;
        }
        acc = warp_sum(acc);
        if (lane == 0) g_rewards[row] = acc;
    }

    // ---- Gate 1: tid0-only release + batch-completion detection ----
    __syncthreads();                 // all block stores happen-before tid0
    const int batch = blockIdx.x / BLOCKS_PER_BATCH;        // 0..63
    if (tid == 0) {
        int pair_todo = -1;
        __threadfence();             // ONE membar per block (release)
        unsigned long long pb = atomicAdd(&g_batch_cnt[batch], 1ULL);
        if (pb % BLOCKS_PER_BATCH == BLOCKS_PER_BATCH - 1) {
            int p = (batch < B_) ? batch : batch - B_;
            unsigned long long pp = atomicAdd(&g_pair_cnt[p], 1ULL);
            if (pp % 2 == 1) pair_todo = p;    // both batches of pair p done
        }
        if (pair_todo >= 0) __threadfence();   // acquire before reading rewards
        s_pair = pair_todo;
    }
    __syncthreads();

    const int p = s_pair;
    if (p < 0) return;

    // ---- Phase B: execute pair p (rewards L2-hot and visible) ----
    if (tid == 0) { sc = S_; sr = S_; sd = S_; }

    // stage both reward rows to smem: 256 thr x 2 float4 per row
    {
        const float4* __restrict__ rc4 =
            reinterpret_cast<const float4*>(g_rewards + (size_t)p * S_);
        const float4* __restrict__ rr4 =
            reinterpret_cast<const float4*>(g_rewards + (size_t)(B_ + p) * S_);
        float4* __restrict__ src4 = reinterpret_cast<float4*>(s_rc);
        float4* __restrict__ srr4 = reinterpret_cast<float4*>(s_rr);
#pragma unroll
        for (int it = 0; it < 2; it++) {
            int v = tid + it * 256;
            src4[v] = rc4[v];
            srr4[v] = rr4[v];
        }
    }

    // id scan: 2 rows x 512 int4, 2 vectors per row per thread
    {
        const int4* __restrict__ idc =
            reinterpret_cast<const int4*>(ids + (size_t)p * S_);
        const int4* __restrict__ idr =
            reinterpret_cast<const int4*>(ids + (size_t)(B_ + p) * S_);
        int cmin = S_, rmin = S_, dmin = S_;
#pragma unroll
        for (int it = 0; it < 2; it++) {
            int v = tid + it * 256;
            int4 c4 = idc[v], r4 = idr[v];
            int s = v * 4;
            if (c4.w == 0) cmin = min(cmin, s + 3);
            if (c4.z == 0) cmin = min(cmin, s + 2);
            if (c4.y == 0) cmin = min(cmin, s + 1);
            if (c4.x == 0) cmin = min(cmin, s + 0);
            if (r4.w == 0) rmin = min(rmin, s + 3);
            if (r4.z == 0) rmin = min(rmin, s + 2);
            if (r4.y == 0) rmin = min(rmin, s + 1);
            if (r4.x == 0) rmin = min(rmin, s + 0);
            if (c4.w != r4.w) dmin = min(dmin, s + 3);
            if (c4.z != r4.z) dmin = min(dmin, s + 2);
            if (c4.y != r4.y) dmin = min(dmin, s + 1);
            if (c4.x != r4.x) dmin = min(dmin, s + 0);
        }
        cmin = warp_min_i(cmin);
        rmin = warp_min_i(rmin);
        dmin = warp_min_i(dmin);
        if (lane == 0) {
            if (cmin < S_) atomicMin(&sc, cmin);
            if (rmin < S_) atomicMin(&sr, rmin);
            if (dmin < S_) atomicMin(&sd, dmin);
        }
    }
    __syncthreads();

    const int  c_ind     = sc;
    const int  r_ind_pad = sr;
    const bool has_div   = sd < S_;
    const int  div_ind   = has_div ? sd : (S_ - 1);
    const int  r_ind     = has_div ? r_ind_pad : c_ind;
    const int  end_ind   = has_div ? max(c_ind, r_ind_pad) : S_;

    float lsum = 0.0f, csum = 0.0f, rsum = 0.0f;
    int   cnt_local = 0;
    for (int s = div_ind + tid; s < end_ind; s += 256) {
        float rc = s_rc[s], rr = s_rr[s];
        float x  = rc - rr;
        // log_sigmoid(x) = min(x,0) - log(1 + exp(-|x|))
        lsum += fminf(x, 0.0f) - __logf(1.0f + __expf(-fabsf(x)));
        csum += __fdividef(1.0f, 1.0f + __expf(-rc));
        rsum += __fdividef(1.0f, 1.0f + __expf(-rr));
        cnt_local++;
    }
    float wl = warp_sum(lsum), wc = warp_sum(csum), wr = warp_sum(rsum);
    int   wn = warp_sum_i(cnt_local);
    if (lane == 0) { sl[warp] = wl; ss1[warp] = wc; ss2[warp] = wr; sn[warp] = wn; }
    __syncthreads();

    if (tid == 0) {
        float L = 0, C = 0, R = 0; int N = 0;
#pragma unroll
        for (int i = 0; i < 8; i++) { L += sl[i]; C += ss1[i]; R += ss2[i]; N += sn[i]; }
        float cnt = fmaxf((float)N, 1.0f);
        g_per_pair[p] = L / cnt;
        g_accflag[p]  = ((C - R) / cnt > 0.5f) ? 1 : 0;
        int ci = c_ind - 1; if (ci < 0) ci = 0; if (ci >= S_) ci = S_ - 1;
        int ri = r_ind - 1; if (ri < 0) ri = 0; if (ri >= S_) ri = S_ - 1;
        out[2 + p]      = s_rc[ci];   // chosen_mean_score
        out[2 + B_ + p] = s_rr[ri];   // rejected_mean_score
        // ---- Gate 2 (tid0 only): last pair triggers final reduction ----
        __threadfence();
        unsigned long long pf = atomicAdd(&g_fin_cnt, 1ULL);
        s_final = (pf % B_ == B_ - 1);
        if (s_final) __threadfence();   // acquire other pairs' scratch
    }
    __syncthreads();

    if (s_final && tid < 32) {
        float pp = g_per_pair[tid];
        int   af = g_accflag[tid];
        float ls = warp_sum(pp);
        int   ac = warp_sum_i(af);
        if (tid == 0) {
            out[0] = -ls;          // loss
            out[1] = (float)ac;    // acc
        }
    }
}

// ---------------------------------------------------------------------------
extern "C" void kernel_launch(void* const* d_in, const int* in_sizes, int n_in,
                              void* d_out, int out_size) {
    const int*   ids = (const int*)d_in[0];     // input_ids  (2B, S) int32
    const float* hs  = (const float*)d_in[1];   // hidden     (2B, S, H) f32
    const float* w   = (const float*)d_in[2];   // w          (H,) f32
    float* out = (float*)d_out;

    fused_kernel<<<NBLOCKS, WARPS_PER_BLOCK * 32>>>(ids, hs, w, out);
}

// round 8
// speedup vs baseline: 1.0716x; 1.0716x over previous
#include <cuda_runtime.h>
#include <math.h>

#define B_ 32
#define S_ 2048
#define H_ 1024
#define NROWS (2 * B_ * S_)   // 131072
#define WARPS_PER_BLOCK 8

// Scratch (allowed: __device__ globals, no allocation). Monotonic counter for
// the finalize gate survives graph replays (modulo test, no reset needed).
__device__ float              g_rewards[NROWS];
__device__ float              g_per_pair[B_];
__device__ int                g_accflag[B_];
__device__ unsigned long long g_fin_cnt;

__device__ __forceinline__ float warp_sum(float v) {
#pragma unroll
    for (int o = 16; o; o >>= 1) v += __shfl_xor_sync(0xffffffffu, v, o);
    return v;
}
__device__ __forceinline__ int warp_sum_i(int v) {
#pragma unroll
    for (int o = 16; o; o >>= 1) v += __shfl_xor_sync(0xffffffffu, v, o);
    return v;
}
__device__ __forceinline__ int warp_min_i(int v) {
#pragma unroll
    for (int o = 16; o; o >>= 1) v = min(v, __shfl_xor_sync(0xffffffffu, v, o));
    return v;
}

// ---------------------------------------------------------------------------
// Kernel 1: rewards[row] = dot(hidden[row, :], w)   (HBM-bound, 512 MB read)
// One warp per row, flat grid — the exact R1/R3 form (85.3% DRAM). No gating,
// no fences, nothing else in the hot path.
// ---------------------------------------------------------------------------
__global__ void __launch_bounds__(WARPS_PER_BLOCK * 32)
reward_dot_kernel(const float* __restrict__ hs, const float* __restrict__ w) {
    __shared__ float4 sw[H_ / 4];
    for (int i = threadIdx.x; i < H_ / 4; i += blockDim.x)
        sw[i] = reinterpret_cast<const float4*>(w)[i];
    __syncthreads();

    const int warp = threadIdx.x >> 5;
    const int lane = threadIdx.x & 31;
    const int row  = blockIdx.x * WARPS_PER_BLOCK + warp;   // grid exact

    const float4* __restrict__ hp =
        reinterpret_cast<const float4*>(hs + (size_t)row * H_);

    float acc = 0.0f;
#pragma unroll
    for (int i = 0; i < 8; i++) {
        float4 h  = __ldcs(&hp[lane + i * 32]);   // streaming, no reuse
        float4 ww = sw[lane + i * 32];
        acc += h.x * ww.x + h.y * ww.y + h.z * ww.z + h.w * ww.w;
    }
    acc = warp_sum(acc);
    if (lane == 0) g_rewards[row] = acc;
}

// ---------------------------------------------------------------------------
// Kernel 2 (PDL secondary): per-pair scan + masked sums + fused finalize.
// Pre-sync phase (overlapped with the dot kernel): id scan from gmem.
// cudaGridDependencySynchronize() -> rewards complete and visible.
// Post-sync phase: L2-hot reward staging + sums + last-block finalize.
// ---------------------------------------------------------------------------
__global__ void __launch_bounds__(1024)
pair_kernel(const int* __restrict__ ids, float* __restrict__ out) {
    const int b    = blockIdx.x;
    const int tid  = threadIdx.x;
    const int warp = tid >> 5;
    const int lane = tid & 31;

    __shared__ __align__(16) float s_rc[S_];
    __shared__ __align__(16) float s_rr[S_];
    __shared__ int   sc, sr, sd;
    __shared__ float sl[32], ss1[32], ss2[32];
    __shared__ int   sn[32];
    __shared__ bool  s_last;

    if (tid == 0) { sc = S_; sr = S_; sd = S_; }
    __syncthreads();

    // ---- pre-sync: id scan (independent of rewards; overlaps dot kernel) ---
    {
        // 1024 threads: tid<512 scan chosen row, tid>=512 scan rejected row.
        const bool is_c = tid < 512;
        const int  v    = is_c ? tid : tid - 512;   // int4 index 0..511
        const int4* __restrict__ idp = reinterpret_cast<const int4*>(
            ids + (size_t)(is_c ? b : B_ + b) * S_);
        // also need the OTHER row's vector for the divergence test
        const int4* __restrict__ idq = reinterpret_cast<const int4*>(
            ids + (size_t)(is_c ? B_ + b : b) * S_);
        int4 a4 = idp[v];
        int4 o4 = idq[v];
        const int s = v * 4;
        int pmin = S_, dmin = S_;
        if (a4.w == 0) pmin = s + 3;
        if (a4.z == 0) pmin = s + 2;
        if (a4.y == 0) pmin = s + 1;
        if (a4.x == 0) pmin = s + 0;
        if (a4.w != o4.w) dmin = s + 3;
        if (a4.z != o4.z) dmin = s + 2;
        if (a4.y != o4.y) dmin = s + 1;
        if (a4.x != o4.x) dmin = s + 0;
        pmin = warp_min_i(pmin);
        dmin = warp_min_i(dmin);
        if (lane == 0) {
            if (pmin < S_) atomicMin(is_c ? &sc : &sr, pmin);
            if (dmin < S_) atomicMin(&sd, dmin);   // both halves agree on diff
        }
    }

    // ---- wait for the dot kernel to complete (rewards visible) ----
    cudaGridDependencySynchronize();
    __syncthreads();

    // ---- stage both reward rows: 1024 threads x 1 float4 (L2-hot) ----
    {
        const float4* __restrict__ rc4 =
            reinterpret_cast<const float4*>(g_rewards + (size_t)b * S_);
        const float4* __restrict__ rr4 =
            reinterpret_cast<const float4*>(g_rewards + (size_t)(B_ + b) * S_);
        if (tid < 512) reinterpret_cast<float4*>(s_rc)[tid]       = rc4[tid];
        else           reinterpret_cast<float4*>(s_rr)[tid - 512] = rr4[tid - 512];
    }
    __syncthreads();

    const int  c_ind     = sc;
    const int  r_ind_pad = sr;
    const bool has_div   = sd < S_;
    const int  div_ind   = has_div ? sd : (S_ - 1);
    const int  r_ind     = has_div ? r_ind_pad : c_ind;
    const int  end_ind   = has_div ? max(c_ind, r_ind_pad) : S_;

    float lsum = 0.0f, csum = 0.0f, rsum = 0.0f;
    int   cnt_local = 0;
    for (int s = div_ind + tid; s < end_ind; s += 1024) {
        float rc = s_rc[s], rr = s_rr[s];
        float x  = rc - rr;
        // log_sigmoid(x) = min(x,0) - log(1 + exp(-|x|))
        lsum += fminf(x, 0.0f) - __logf(1.0f + __expf(-fabsf(x)));
        csum += __fdividef(1.0f, 1.0f + __expf(-rc));
        rsum += __fdividef(1.0f, 1.0f + __expf(-rr));
        cnt_local++;
    }

    float wl = warp_sum(lsum), wc = warp_sum(csum), wr = warp_sum(rsum);
    int   wn = warp_sum_i(cnt_local);
    if (lane == 0) { sl[warp] = wl; ss1[warp] = wc; ss2[warp] = wr; sn[warp] = wn; }
    __syncthreads();

    if (tid == 0) {
        float L = 0, C = 0, R = 0; int N = 0;
#pragma unroll
        for (int i = 0; i < 32; i++) { L += sl[i]; C += ss1[i]; R += ss2[i]; N += sn[i]; }
        float cnt = fmaxf((float)N, 1.0f);
        g_per_pair[b] = L / cnt;
        g_accflag[b]  = ((C - R) / cnt > 0.5f) ? 1 : 0;
        int ci = c_ind - 1; if (ci < 0) ci = 0; if (ci >= S_) ci = S_ - 1;
        int ri = r_ind - 1; if (ri < 0) ri = 0; if (ri >= S_) ri = S_ - 1;
        out[2 + b]      = s_rc[ci];   // chosen_mean_score
        out[2 + B_ + b] = s_rr[ri];   // rejected_mean_score
        __threadfence();
        unsigned long long pf = atomicAdd(&g_fin_cnt, 1ULL);
        s_last = (pf % B_ == (unsigned long long)(B_ - 1));
        if (s_last) __threadfence();   // acquire other pairs' scratch
    }
    __syncthreads();

    // Last block to finish: deterministic final reduction (fixed order)
    if (s_last && tid < 32) {
        float pp = g_per_pair[tid];
        int   af = g_accflag[tid];
        float ls = warp_sum(pp);
        int   ac = warp_sum_i(af);
        if (tid == 0) {
            out[0] = -ls;          // loss
            out[1] = (float)ac;    // acc
        }
    }
}

// ---------------------------------------------------------------------------
extern "C" void kernel_launch(void* const* d_in, const int* in_sizes, int n_in,
                              void* d_out, int out_size) {
    const int*   ids = (const int*)d_in[0];     // input_ids  (2B, S) int32
    const float* hs  = (const float*)d_in[1];   // hidden     (2B, S, H) f32
    const float* w   = (const float*)d_in[2];   // w          (H,) f32
    float* out = (float*)d_out;

    const int blocks = NROWS / WARPS_PER_BLOCK;   // 16384
    reward_dot_kernel<<<blocks, WARPS_PER_BLOCK * 32>>>(hs, w);

    // PDL secondary: may start while the dot kernel drains; its pre-sync id
    // scan overlaps; cudaGridDependencySynchronize() gates the reward reads.
    cudaLaunchConfig_t cfg = {};
    cfg.gridDim  = dim3(B_);
    cfg.blockDim = dim3(1024);
    cudaLaunchAttribute attr[1];
    attr[0].id = cudaLaunchAttributeProgrammaticStreamSerialization;
    attr[0].val.programmaticStreamSerializationAllowed = 1;
    cfg.attrs    = attr;
    cfg.numAttrs = 1;
    cudaLaunchKernelEx(&cfg, pair_kernel, ids, out);
}